// round 1
// baseline (speedup 1.0000x reference)
#include <cuda_runtime.h>
#include <math_constants.h>

#define BATCH  4
#define SEQ    2048
#define DMODEL 1024
#define NHEAD  16
#define HDIM   64
#define MROWS  (BATCH * SEQ)   // 8192

// Scratch: Q/K/V in [B, H, S, HDIM] layout, fp32. 32 MB each.
__device__ float g_Q[(size_t)MROWS * DMODEL];
__device__ float g_K[(size_t)MROWS * DMODEL];
__device__ float g_V[(size_t)MROWS * DMODEL];

// ---------------------------------------------------------------------------
// Projection: dst[b,h,s,d] = sum_k X[m,k] * W[n,k] + b[n],  n = h*64+d
// block: 64 threads, each owns one m-row, accumulates 64 n-columns.
// grid: (MROWS/64, NHEAD, 3)  z selects Q/K/V.
// ---------------------------------------------------------------------------
__global__ __launch_bounds__(64)
void proj_kernel(const float* __restrict__ X,
                 const float* __restrict__ Wq, const float* __restrict__ bq,
                 const float* __restrict__ Wk, const float* __restrict__ bk,
                 const float* __restrict__ Wv, const float* __restrict__ bv)
{
    const float* W; const float* bias; float* dst; float scale;
    if (blockIdx.z == 0)      { W = Wq; bias = bq; dst = g_Q; scale = 0.125f; } // 1/sqrt(64) folded into Q
    else if (blockIdx.z == 1) { W = Wk; bias = bk; dst = g_K; scale = 1.0f; }
    else                      { W = Wv; bias = bv; dst = g_V; scale = 1.0f; }

    const int t  = threadIdx.x;
    const int m  = blockIdx.x * 64 + t;
    const int n0 = blockIdx.y * 64;

    __shared__ float4 Wt[64 * 8];   // 64 n-rows x 32 k (as 8 float4 per row)

    float acc[64];
#pragma unroll
    for (int n = 0; n < 64; n++) acc[n] = 0.f;

    const float* xrow = X + (size_t)m * DMODEL;

    for (int k0 = 0; k0 < DMODEL; k0 += 32) {
        __syncthreads();
#pragma unroll
        for (int i = 0; i < 8; i++) {
            int f  = i * 64 + t;          // float4 index within tile (coalesced fill)
            int n  = f >> 3;
            int c4 = f & 7;
            Wt[f] = *(const float4*)(W + (size_t)(n0 + n) * DMODEL + k0 + c4 * 4);
        }
        __syncthreads();

        float4 x[8];
#pragma unroll
        for (int i = 0; i < 8; i++)
            x[i] = *(const float4*)(xrow + k0 + i * 4);

#pragma unroll 4
        for (int n = 0; n < 64; n++) {
#pragma unroll
            for (int i = 0; i < 8; i++) {
                float4 w = Wt[n * 8 + i];   // broadcast LDS: all lanes same addr
                acc[n] += x[i].x * w.x;
                acc[n] += x[i].y * w.y;
                acc[n] += x[i].z * w.z;
                acc[n] += x[i].w * w.w;
            }
        }
    }

    const int bb = m / SEQ, ss = m % SEQ;
    float* drow = dst + ((size_t)(bb * NHEAD + blockIdx.y) * SEQ + ss) * HDIM;
#pragma unroll
    for (int i = 0; i < 16; i++) {
        float4 r;
        r.x = (acc[i*4+0] + bias[n0 + i*4+0]) * scale;
        r.y = (acc[i*4+1] + bias[n0 + i*4+1]) * scale;
        r.z = (acc[i*4+2] + bias[n0 + i*4+2]) * scale;
        r.w = (acc[i*4+3] + bias[n0 + i*4+3]) * scale;
        ((float4*)drow)[i] = r;
    }
}

// ---------------------------------------------------------------------------
// Flash attention: block = (b, h, 64 q-rows); 64 threads, thread t owns q-row t.
// K/V streamed through smem in 32-row tiles; online softmax in registers.
// grid: (SEQ/64, NHEAD, BATCH)
// ---------------------------------------------------------------------------
__global__ __launch_bounds__(64)
void attn_kernel(float* __restrict__ out)
{
    const int t = threadIdx.x;
    const int h = blockIdx.y, b = blockIdx.z;
    const int s = blockIdx.x * 64 + t;

    const float* Qb = g_Q + (size_t)(b * NHEAD + h) * SEQ * HDIM;
    const float* Kb = g_K + (size_t)(b * NHEAD + h) * SEQ * HDIM;
    const float* Vb = g_V + (size_t)(b * NHEAD + h) * SEQ * HDIM;

    __shared__ float4 q_s[64 * 17];   // 64 rows x (16 + 1 pad) float4 -> 17 odd: conflict-free per-row reads
    __shared__ float4 k_s[32 * 16];   // 32 kv rows x 64 floats
    __shared__ float4 v_s[32 * 16];

    // Load this block's q rows (row t -> q_s row t)
    {
        const float4* qr = (const float4*)(Qb + (size_t)s * HDIM);
#pragma unroll
        for (int i = 0; i < 16; i++) q_s[t * 17 + i] = qr[i];
    }

    float o[64];
#pragma unroll
    for (int c = 0; c < 64; c++) o[c] = 0.f;
    float mrun = -CUDART_INF_F;
    float l = 0.f;

    for (int kt = 0; kt < SEQ; kt += 32) {
        __syncthreads();
#pragma unroll
        for (int i = 0; i < 8; i++) {
            int f = i * 64 + t;           // coalesced tile fill
            k_s[f] = *(const float4*)(Kb + (size_t)kt * HDIM + f * 4);
            v_s[f] = *(const float4*)(Vb + (size_t)kt * HDIM + f * 4);
        }
        __syncthreads();

        // scores: sc[j] = q_row . k_row_j   (q pre-scaled by 1/8)
        float sc[32];
#pragma unroll
        for (int j = 0; j < 32; j++) sc[j] = 0.f;

        for (int d4 = 0; d4 < 16; d4++) {
            float4 q = q_s[t * 17 + d4];
#pragma unroll
            for (int j = 0; j < 32; j++) {
                float4 k = k_s[j * 16 + d4];   // broadcast LDS
                sc[j] += q.x * k.x;
                sc[j] += q.y * k.y;
                sc[j] += q.z * k.z;
                sc[j] += q.w * k.w;
            }
        }

        // online softmax update
        float mt = mrun;
#pragma unroll
        for (int j = 0; j < 32; j++) mt = fmaxf(mt, sc[j]);
        float corr = __expf(mrun - mt);   // first tile: exp(-inf) = 0
        mrun = mt;
        l *= corr;
#pragma unroll
        for (int j = 0; j < 32; j++) { float p = __expf(sc[j] - mt); l += p; sc[j] = p; }
#pragma unroll
        for (int c = 0; c < 64; c++) o[c] *= corr;

        // o += P @ V
        for (int j = 0; j < 32; j++) {
            float p = sc[j];
#pragma unroll
            for (int i = 0; i < 16; i++) {
                float4 v = v_s[j * 16 + i];    // broadcast LDS
                o[i*4+0] += p * v.x;
                o[i*4+1] += p * v.y;
                o[i*4+2] += p * v.z;
                o[i*4+3] += p * v.w;
            }
        }
    }

    // write out[b, s, h*64 + c] = o[c] / l   (merged heads)
    float inv = 1.0f / l;
    float* orow = out + (size_t)(b * SEQ + s) * DMODEL + h * HDIM;
#pragma unroll
    for (int i = 0; i < 16; i++) {
        float4 r;
        r.x = o[i*4+0] * inv;
        r.y = o[i*4+1] * inv;
        r.z = o[i*4+2] * inv;
        r.w = o[i*4+3] * inv;
        ((float4*)orow)[i] = r;
    }
}

// ---------------------------------------------------------------------------
extern "C" void kernel_launch(void* const* d_in, const int* in_sizes, int n_in,
                              void* d_out, int out_size)
{
    const float* X  = (const float*)d_in[0];
    const float* Wq = (const float*)d_in[1];
    const float* bq = (const float*)d_in[2];
    const float* Wk = (const float*)d_in[3];
    const float* bk = (const float*)d_in[4];
    const float* Wv = (const float*)d_in[5];
    const float* bv = (const float*)d_in[6];
    float* out = (float*)d_out;

    proj_kernel<<<dim3(MROWS / 64, NHEAD, 3), 64>>>(X, Wq, bq, Wk, bk, Wv, bv);
    attn_kernel<<<dim3(SEQ / 64, NHEAD, BATCH), 64>>>(out);
}

// round 3
// speedup vs baseline: 1.3448x; 1.3448x over previous
#include <cuda_runtime.h>
#include <cuda_bf16.h>
#include <math_constants.h>
#include <cstdint>

#define BATCH  4
#define SEQ    2048
#define DMODEL 1024
#define NHEAD  16
#define HDIM   64
#define MROWS  (BATCH * SEQ)   // 8192

// ---------------------------------------------------------------------------
// Scratch
// ---------------------------------------------------------------------------
__device__ float g_Q[(size_t)MROWS * DMODEL];
__device__ float g_K[(size_t)MROWS * DMODEL];
__device__ float g_V[(size_t)MROWS * DMODEL];

__device__ __nv_bfloat16 g_Xh[(size_t)MROWS * DMODEL];
__device__ __nv_bfloat16 g_Xl[(size_t)MROWS * DMODEL];
__device__ __nv_bfloat16 g_Wh[(size_t)3 * DMODEL * DMODEL];
__device__ __nv_bfloat16 g_Wl[(size_t)3 * DMODEL * DMODEL];

#define SMEM_SWIZZLE_128B(o) ((o) ^ (((o) >> 3) & 0x70))

__device__ __forceinline__ uint32_t smem_u32(const void* p) {
    uint32_t a;
    asm("{ .reg .u64 t; cvta.to.shared.u64 t, %1; cvt.u32.u64 %0, t; }" : "=r"(a) : "l"(p));
    return a;
}

__device__ __forceinline__ void ldmx4(uint32_t* r, uint32_t addr) {
    asm volatile("ldmatrix.sync.aligned.m8n8.x4.shared.b16 {%0,%1,%2,%3}, [%4];"
                 : "=r"(r[0]), "=r"(r[1]), "=r"(r[2]), "=r"(r[3]) : "r"(addr));
}

__device__ __forceinline__ void mma_bf16(float* c, const uint32_t* a, const uint32_t* b) {
    asm volatile(
        "mma.sync.aligned.m16n8k16.row.col.f32.bf16.bf16.f32 "
        "{%0,%1,%2,%3}, {%4,%5,%6,%7}, {%8,%9}, {%0,%1,%2,%3};"
        : "+f"(c[0]), "+f"(c[1]), "+f"(c[2]), "+f"(c[3])
        : "r"(a[0]), "r"(a[1]), "r"(a[2]), "r"(a[3]), "r"(b[0]), "r"(b[1]));
}

// ---------------------------------------------------------------------------
// fp32 -> bf16 hi/lo split converters
// ---------------------------------------------------------------------------
__global__ __launch_bounds__(256)
void convert_x_kernel(const float* __restrict__ X)
{
    size_t i = ((size_t)blockIdx.x * 256 + threadIdx.x) * 4;
    float4 v = *(const float4*)(X + i);
    __nv_bfloat16 h0 = __float2bfloat16(v.x);
    __nv_bfloat16 h1 = __float2bfloat16(v.y);
    __nv_bfloat16 h2 = __float2bfloat16(v.z);
    __nv_bfloat16 h3 = __float2bfloat16(v.w);
    __nv_bfloat16 l0 = __float2bfloat16(v.x - __bfloat162float(h0));
    __nv_bfloat16 l1 = __float2bfloat16(v.y - __bfloat162float(h1));
    __nv_bfloat16 l2 = __float2bfloat16(v.z - __bfloat162float(h2));
    __nv_bfloat16 l3 = __float2bfloat16(v.w - __bfloat162float(h3));
    __nv_bfloat162* ph = (__nv_bfloat162*)(g_Xh + i);
    __nv_bfloat162* pl = (__nv_bfloat162*)(g_Xl + i);
    ph[0] = __halves2bfloat162(h0, h1); ph[1] = __halves2bfloat162(h2, h3);
    pl[0] = __halves2bfloat162(l0, l1); pl[1] = __halves2bfloat162(l2, l3);
}

__global__ __launch_bounds__(256)
void convert_w_kernel(const float* __restrict__ Wq,
                      const float* __restrict__ Wk,
                      const float* __restrict__ Wv)
{
    int z = blockIdx.y;
    const float* W = (z == 0) ? Wq : (z == 1) ? Wk : Wv;
    size_t i = ((size_t)blockIdx.x * 256 + threadIdx.x) * 4;
    float4 v = *(const float4*)(W + i);
    size_t o = (size_t)z * DMODEL * DMODEL + i;
    __nv_bfloat16 h0 = __float2bfloat16(v.x);
    __nv_bfloat16 h1 = __float2bfloat16(v.y);
    __nv_bfloat16 h2 = __float2bfloat16(v.z);
    __nv_bfloat16 h3 = __float2bfloat16(v.w);
    __nv_bfloat16 l0 = __float2bfloat16(v.x - __bfloat162float(h0));
    __nv_bfloat16 l1 = __float2bfloat16(v.y - __bfloat162float(h1));
    __nv_bfloat16 l2 = __float2bfloat16(v.z - __bfloat162float(h2));
    __nv_bfloat16 l3 = __float2bfloat16(v.w - __bfloat162float(h3));
    __nv_bfloat162* ph = (__nv_bfloat162*)(g_Wh + o);
    __nv_bfloat162* pl = (__nv_bfloat162*)(g_Wl + o);
    ph[0] = __halves2bfloat162(h0, h1); ph[1] = __halves2bfloat162(h2, h3);
    pl[0] = __halves2bfloat162(l0, l1); pl[1] = __halves2bfloat162(l2, l3);
}

// ---------------------------------------------------------------------------
// Projection GEMM via mma.sync bf16 (hi/lo split, fp32 accum).
// C[8192, 3072] = X * [Wq|Wk|Wv]^T.  CTA tile 128x128, warp tile 32x64.
// grid (64, 24), 256 threads. Epilogue scatters to g_Q/g_K/g_V in [B,H,S,64].
// ---------------------------------------------------------------------------
#define PROJ_SMEM_BYTES (1024 + 65536)

__global__ __launch_bounds__(256, 2)
void proj_mma_kernel(const float* __restrict__ bq,
                     const float* __restrict__ bk,
                     const float* __restrict__ bv)
{
    extern __shared__ __align__(16) char smem_raw[];
    char* tile = (char*)(((uintptr_t)smem_raw + 1023) & ~(uintptr_t)1023);
    const uint32_t sbase = smem_u32(tile);
    // layout: Ah[16K] Al[16K] Bh[16K] Bl[16K]

    const int tid  = threadIdx.x;
    const int wid  = tid >> 5;
    const int lane = tid & 31;
    const int warp_m = wid & 3;    // 4 warps along M (32 rows each)
    const int warp_n = wid >> 2;   // 2 warps along N (64 cols each)

    const int m0 = blockIdx.x * 128;
    const int n0 = blockIdx.y * 128;          // global n in [0, 3072)
    const int z  = n0 >> 10;                  // 0:Q 1:K 2:V
    const int n_in_base = (n0 & 1023) + warp_n * 64;  // within [0,1024), multiple of 64

    float acc[2][8][4];
#pragma unroll
    for (int mi = 0; mi < 2; mi++)
#pragma unroll
        for (int nb = 0; nb < 8; nb++)
#pragma unroll
            for (int q = 0; q < 4; q++) acc[mi][nb][q] = 0.f;

    for (int kc = 0; kc < 16; kc++) {
        const int k0 = kc * 64;
        __syncthreads();
        // Stage tiles: 128 rows x 64 bf16 (=128B/row, SW128 swizzled), x4 regions
#pragma unroll
        for (int i = 0; i < 4; i++) {
            int idx = i * 256 + tid;
            int r = idx >> 3, c8 = (idx & 7) * 8;
            uint32_t so = SMEM_SWIZZLE_128B((uint32_t)(r * 128 + c8 * 2));
            size_t ga = (size_t)(m0 + r) * DMODEL + k0 + c8;
            size_t gb = (size_t)(n0 + r) * DMODEL + k0 + c8;
            *(uint4*)(tile + so)         = *(const uint4*)(g_Xh + ga);
            *(uint4*)(tile + 16384 + so) = *(const uint4*)(g_Xl + ga);
            *(uint4*)(tile + 32768 + so) = *(const uint4*)(g_Wh + gb);
            *(uint4*)(tile + 49152 + so) = *(const uint4*)(g_Wl + gb);
        }
        __syncthreads();

#pragma unroll
        for (int pass = 0; pass < 3; pass++) {
            const uint32_t abase = sbase + ((pass == 2) ? 16384u : 0u);
            const uint32_t bbase = sbase + 32768u + ((pass == 1) ? 16384u : 0u);
#pragma unroll
            for (int ks = 0; ks < 4; ks++) {
                uint32_t afr[2][4];
#pragma unroll
                for (int mi = 0; mi < 2; mi++) {
                    uint32_t off = (uint32_t)((warp_m * 32 + mi * 16 + (lane & 15)) * 128
                                              + ks * 32 + (lane >> 4) * 16);
                    ldmx4(afr[mi], abase + SMEM_SWIZZLE_128B(off));
                }
                uint32_t bfr[8][2];
#pragma unroll
                for (int pr = 0; pr < 4; pr++) {
                    uint32_t row = (uint32_t)(warp_n * 64 + pr * 16 + (lane & 7) + ((lane >> 4) << 3));
                    uint32_t off = row * 128 + ks * 32 + (((lane >> 3) & 1) << 4);
                    uint32_t r4[4];
                    ldmx4(r4, bbase + SMEM_SWIZZLE_128B(off));
                    bfr[pr * 2 + 0][0] = r4[0]; bfr[pr * 2 + 0][1] = r4[1];
                    bfr[pr * 2 + 1][0] = r4[2]; bfr[pr * 2 + 1][1] = r4[3];
                }
#pragma unroll
                for (int mi = 0; mi < 2; mi++)
#pragma unroll
                    for (int nb = 0; nb < 8; nb++)
                        mma_bf16(acc[mi][nb], afr[mi], bfr[nb]);
            }
        }
    }

    // Epilogue: scatter to g_Q/g_K/g_V as [B,H,S,64] fp32, bias + Q scale.
    float* dst = (z == 0) ? g_Q : (z == 1) ? g_K : g_V;
    const float* bias = (z == 0) ? bq : (z == 1) ? bk : bv;
    const float scale = (z == 0) ? 0.125f : 1.0f;
    const int h = n_in_base >> 6;           // one head per warp (n tile = 64)

#pragma unroll
    for (int mi = 0; mi < 2; mi++) {
#pragma unroll
        for (int half = 0; half < 2; half++) {
            int row = m0 + warp_m * 32 + mi * 16 + (lane >> 2) + half * 8;
            int b = row >> 11, s = row & 2047;
            float* orow = dst + ((size_t)((b * NHEAD + h) * SEQ + s)) * HDIM;
#pragma unroll
            for (int nb = 0; nb < 8; nb++) {
                int d = nb * 8 + (lane & 3) * 2;
                float2 v;
                v.x = (acc[mi][nb][half * 2 + 0] + bias[n_in_base + d + 0]) * scale;
                v.y = (acc[mi][nb][half * 2 + 1] + bias[n_in_base + d + 1]) * scale;
                *(float2*)(orow + d) = v;
            }
        }
    }
}

// ---------------------------------------------------------------------------
// Flash attention (fp32 SIMT — unchanged, known good)
// ---------------------------------------------------------------------------
__global__ __launch_bounds__(64)
void attn_kernel(float* __restrict__ out)
{
    const int t = threadIdx.x;
    const int h = blockIdx.y, b = blockIdx.z;
    const int s = blockIdx.x * 64 + t;

    const float* Qb = g_Q + (size_t)(b * NHEAD + h) * SEQ * HDIM;
    const float* Kb = g_K + (size_t)(b * NHEAD + h) * SEQ * HDIM;
    const float* Vb = g_V + (size_t)(b * NHEAD + h) * SEQ * HDIM;

    __shared__ float4 q_s[64 * 17];
    __shared__ float4 k_s[32 * 16];
    __shared__ float4 v_s[32 * 16];

    {
        const float4* qr = (const float4*)(Qb + (size_t)s * HDIM);
#pragma unroll
        for (int i = 0; i < 16; i++) q_s[t * 17 + i] = qr[i];
    }

    float o[64];
#pragma unroll
    for (int c = 0; c < 64; c++) o[c] = 0.f;
    float mrun = -CUDART_INF_F;
    float l = 0.f;

    for (int kt = 0; kt < SEQ; kt += 32) {
        __syncthreads();
#pragma unroll
        for (int i = 0; i < 8; i++) {
            int f = i * 64 + t;
            k_s[f] = *(const float4*)(Kb + (size_t)kt * HDIM + f * 4);
            v_s[f] = *(const float4*)(Vb + (size_t)kt * HDIM + f * 4);
        }
        __syncthreads();

        float sc[32];
#pragma unroll
        for (int j = 0; j < 32; j++) sc[j] = 0.f;

        for (int d4 = 0; d4 < 16; d4++) {
            float4 q = q_s[t * 17 + d4];
#pragma unroll
            for (int j = 0; j < 32; j++) {
                float4 k = k_s[j * 16 + d4];
                sc[j] += q.x * k.x;
                sc[j] += q.y * k.y;
                sc[j] += q.z * k.z;
                sc[j] += q.w * k.w;
            }
        }

        float mt = mrun;
#pragma unroll
        for (int j = 0; j < 32; j++) mt = fmaxf(mt, sc[j]);
        float corr = __expf(mrun - mt);
        mrun = mt;
        l *= corr;
#pragma unroll
        for (int j = 0; j < 32; j++) { float p = __expf(sc[j] - mt); l += p; sc[j] = p; }
#pragma unroll
        for (int c = 0; c < 64; c++) o[c] *= corr;

        for (int j = 0; j < 32; j++) {
            float p = sc[j];
#pragma unroll
            for (int i = 0; i < 16; i++) {
                float4 v = v_s[j * 16 + i];
                o[i*4+0] += p * v.x;
                o[i*4+1] += p * v.y;
                o[i*4+2] += p * v.z;
                o[i*4+3] += p * v.w;
            }
        }
    }

    float inv = 1.0f / l;
    float* orow = out + (size_t)(b * SEQ + s) * DMODEL + h * HDIM;
#pragma unroll
    for (int i = 0; i < 16; i++) {
        float4 r;
        r.x = o[i*4+0] * inv;
        r.y = o[i*4+1] * inv;
        r.z = o[i*4+2] * inv;
        r.w = o[i*4+3] * inv;
        ((float4*)orow)[i] = r;
    }
}

// ---------------------------------------------------------------------------
extern "C" void kernel_launch(void* const* d_in, const int* in_sizes, int n_in,
                              void* d_out, int out_size)
{
    const float* X  = (const float*)d_in[0];
    const float* Wq = (const float*)d_in[1];
    const float* bq = (const float*)d_in[2];
    const float* Wk = (const float*)d_in[3];
    const float* bk = (const float*)d_in[4];
    const float* Wv = (const float*)d_in[5];
    const float* bv = (const float*)d_in[6];
    float* out = (float*)d_out;

    cudaFuncSetAttribute(proj_mma_kernel,
                         cudaFuncAttributeMaxDynamicSharedMemorySize, PROJ_SMEM_BYTES);

    convert_x_kernel<<<MROWS * DMODEL / 1024, 256>>>(X);
    convert_w_kernel<<<dim3(DMODEL * DMODEL / 1024, 3), 256>>>(Wq, Wk, Wv);
    proj_mma_kernel<<<dim3(MROWS / 128, 3 * DMODEL / 128), 256, PROJ_SMEM_BYTES>>>(bq, bk, bv);
    attn_kernel<<<dim3(SEQ / 64, NHEAD, BATCH), 64>>>(out);
}

// round 5
// speedup vs baseline: 3.2155x; 2.3910x over previous
#include <cuda_runtime.h>
#include <cuda_bf16.h>
#include <math_constants.h>
#include <cstdint>

#define BATCH  4
#define SEQ    2048
#define DMODEL 1024
#define NHEAD  16
#define HDIM   64
#define MROWS  (BATCH * SEQ)   // 8192

// Q scale folds 1/sqrt(64) and log2(e):  0.125 * 1.4426950408889634
#define QSCALE 0.18033688f

// ---------------------------------------------------------------------------
// Scratch (bf16 hi/lo everywhere)
// ---------------------------------------------------------------------------
__device__ __nv_bfloat16 g_Xh[(size_t)MROWS * DMODEL];
__device__ __nv_bfloat16 g_Xl[(size_t)MROWS * DMODEL];
__device__ __nv_bfloat16 g_Wh[(size_t)3 * DMODEL * DMODEL];
__device__ __nv_bfloat16 g_Wl[(size_t)3 * DMODEL * DMODEL];

__device__ __nv_bfloat16 g_Qh[(size_t)MROWS * HDIM * NHEAD];
__device__ __nv_bfloat16 g_Ql[(size_t)MROWS * HDIM * NHEAD];
__device__ __nv_bfloat16 g_Kh[(size_t)MROWS * HDIM * NHEAD];
__device__ __nv_bfloat16 g_Kl[(size_t)MROWS * HDIM * NHEAD];
__device__ __nv_bfloat16 g_Vh[(size_t)MROWS * HDIM * NHEAD];
__device__ __nv_bfloat16 g_Vl[(size_t)MROWS * HDIM * NHEAD];

#define SMEM_SWIZZLE_128B(o) ((o) ^ (((o) >> 3) & 0x70))

__device__ __forceinline__ uint32_t smem_u32(const void* p) {
    uint32_t a;
    asm("{ .reg .u64 t; cvta.to.shared.u64 t, %1; cvt.u32.u64 %0, t; }" : "=r"(a) : "l"(p));
    return a;
}

__device__ __forceinline__ void ldmx4(uint32_t* r, uint32_t addr) {
    asm volatile("ldmatrix.sync.aligned.m8n8.x4.shared.b16 {%0,%1,%2,%3}, [%4];"
                 : "=r"(r[0]), "=r"(r[1]), "=r"(r[2]), "=r"(r[3]) : "r"(addr));
}
__device__ __forceinline__ void ldmx4t(uint32_t* r, uint32_t addr) {
    asm volatile("ldmatrix.sync.aligned.m8n8.x4.trans.shared.b16 {%0,%1,%2,%3}, [%4];"
                 : "=r"(r[0]), "=r"(r[1]), "=r"(r[2]), "=r"(r[3]) : "r"(addr));
}

__device__ __forceinline__ void mma_bf16(float* c, const uint32_t* a, const uint32_t* b) {
    asm volatile(
        "mma.sync.aligned.m16n8k16.row.col.f32.bf16.bf16.f32 "
        "{%0,%1,%2,%3}, {%4,%5,%6,%7}, {%8,%9}, {%0,%1,%2,%3};"
        : "+f"(c[0]), "+f"(c[1]), "+f"(c[2]), "+f"(c[3])
        : "r"(a[0]), "r"(a[1]), "r"(a[2]), "r"(a[3]), "r"(b[0]), "r"(b[1]));
}

__device__ __forceinline__ uint32_t pack_bf16(float lo, float hi) {
    uint32_t d;
    asm("cvt.rn.bf16x2.f32 %0, %1, %2;" : "=r"(d) : "f"(hi), "f"(lo));
    return d;
}

__device__ __forceinline__ void cp_async16(uint32_t saddr, const void* gaddr) {
    asm volatile("cp.async.cg.shared.global [%0], [%1], 16;" :: "r"(saddr), "l"(gaddr));
}

// ---------------------------------------------------------------------------
// fp32 -> bf16 hi/lo split converters
// ---------------------------------------------------------------------------
__global__ __launch_bounds__(256)
void convert_x_kernel(const float* __restrict__ X)
{
    size_t i = ((size_t)blockIdx.x * 256 + threadIdx.x) * 4;
    float4 v = *(const float4*)(X + i);
    __nv_bfloat16 h0 = __float2bfloat16(v.x);
    __nv_bfloat16 h1 = __float2bfloat16(v.y);
    __nv_bfloat16 h2 = __float2bfloat16(v.z);
    __nv_bfloat16 h3 = __float2bfloat16(v.w);
    __nv_bfloat16 l0 = __float2bfloat16(v.x - __bfloat162float(h0));
    __nv_bfloat16 l1 = __float2bfloat16(v.y - __bfloat162float(h1));
    __nv_bfloat16 l2 = __float2bfloat16(v.z - __bfloat162float(h2));
    __nv_bfloat16 l3 = __float2bfloat16(v.w - __bfloat162float(h3));
    __nv_bfloat162* ph = (__nv_bfloat162*)(g_Xh + i);
    __nv_bfloat162* pl = (__nv_bfloat162*)(g_Xl + i);
    ph[0] = __halves2bfloat162(h0, h1); ph[1] = __halves2bfloat162(h2, h3);
    pl[0] = __halves2bfloat162(l0, l1); pl[1] = __halves2bfloat162(l2, l3);
}

__global__ __launch_bounds__(256)
void convert_w_kernel(const float* __restrict__ Wq,
                      const float* __restrict__ Wk,
                      const float* __restrict__ Wv)
{
    int z = blockIdx.y;
    const float* W = (z == 0) ? Wq : (z == 1) ? Wk : Wv;
    size_t i = ((size_t)blockIdx.x * 256 + threadIdx.x) * 4;
    float4 v = *(const float4*)(W + i);
    size_t o = (size_t)z * DMODEL * DMODEL + i;
    __nv_bfloat16 h0 = __float2bfloat16(v.x);
    __nv_bfloat16 h1 = __float2bfloat16(v.y);
    __nv_bfloat16 h2 = __float2bfloat16(v.z);
    __nv_bfloat16 h3 = __float2bfloat16(v.w);
    __nv_bfloat16 l0 = __float2bfloat16(v.x - __bfloat162float(h0));
    __nv_bfloat16 l1 = __float2bfloat16(v.y - __bfloat162float(h1));
    __nv_bfloat16 l2 = __float2bfloat16(v.z - __bfloat162float(h2));
    __nv_bfloat16 l3 = __float2bfloat16(v.w - __bfloat162float(h3));
    __nv_bfloat162* ph = (__nv_bfloat162*)(g_Wh + o);
    __nv_bfloat162* pl = (__nv_bfloat162*)(g_Wl + o);
    ph[0] = __halves2bfloat162(h0, h1); ph[1] = __halves2bfloat162(h2, h3);
    pl[0] = __halves2bfloat162(l0, l1); pl[1] = __halves2bfloat162(l2, l3);
}

// ---------------------------------------------------------------------------
// Projection GEMM via mma.sync bf16 (hi/lo split, fp32 accum).
// C[8192, 3072] = X * [Wq|Wk|Wv]^T.  CTA tile 128x128, warp tile 32x64.
// Epilogue writes bf16 hi/lo Q/K/V in [B,H,S,64]; Q scaled by QSCALE.
// ---------------------------------------------------------------------------
#define PROJ_SMEM_BYTES (1024 + 65536)

__global__ __launch_bounds__(256, 2)
void proj_mma_kernel(const float* __restrict__ bq,
                     const float* __restrict__ bk,
                     const float* __restrict__ bv)
{
    extern __shared__ __align__(16) char smem_raw[];
    char* tile = (char*)(((uintptr_t)smem_raw + 1023) & ~(uintptr_t)1023);
    const uint32_t sbase = smem_u32(tile);

    const int tid  = threadIdx.x;
    const int wid  = tid >> 5;
    const int lane = tid & 31;
    const int warp_m = wid & 3;
    const int warp_n = wid >> 2;

    const int m0 = blockIdx.x * 128;
    const int n0 = blockIdx.y * 128;
    const int z  = n0 >> 10;
    const int n_in_base = (n0 & 1023) + warp_n * 64;

    float acc[2][8][4];
#pragma unroll
    for (int mi = 0; mi < 2; mi++)
#pragma unroll
        for (int nb = 0; nb < 8; nb++)
#pragma unroll
            for (int q = 0; q < 4; q++) acc[mi][nb][q] = 0.f;

    for (int kc = 0; kc < 16; kc++) {
        const int k0 = kc * 64;
        __syncthreads();
#pragma unroll
        for (int i = 0; i < 4; i++) {
            int idx = i * 256 + tid;
            int r = idx >> 3, c8 = (idx & 7) * 8;
            uint32_t so = SMEM_SWIZZLE_128B((uint32_t)(r * 128 + c8 * 2));
            size_t ga = (size_t)(m0 + r) * DMODEL + k0 + c8;
            size_t gb = (size_t)(n0 + r) * DMODEL + k0 + c8;
            *(uint4*)(tile + so)         = *(const uint4*)(g_Xh + ga);
            *(uint4*)(tile + 16384 + so) = *(const uint4*)(g_Xl + ga);
            *(uint4*)(tile + 32768 + so) = *(const uint4*)(g_Wh + gb);
            *(uint4*)(tile + 49152 + so) = *(const uint4*)(g_Wl + gb);
        }
        __syncthreads();

#pragma unroll
        for (int pass = 0; pass < 3; pass++) {
            const uint32_t abase = sbase + ((pass == 2) ? 16384u : 0u);
            const uint32_t bbase = sbase + 32768u + ((pass == 1) ? 16384u : 0u);
#pragma unroll
            for (int ks = 0; ks < 4; ks++) {
                uint32_t afr[2][4];
#pragma unroll
                for (int mi = 0; mi < 2; mi++) {
                    uint32_t off = (uint32_t)((warp_m * 32 + mi * 16 + (lane & 15)) * 128
                                              + ks * 32 + (lane >> 4) * 16);
                    ldmx4(afr[mi], abase + SMEM_SWIZZLE_128B(off));
                }
                uint32_t bfr[8][2];
#pragma unroll
                for (int pr = 0; pr < 4; pr++) {
                    uint32_t row = (uint32_t)(warp_n * 64 + pr * 16 + (lane & 7) + ((lane >> 4) << 3));
                    uint32_t off = row * 128 + ks * 32 + (((lane >> 3) & 1) << 4);
                    uint32_t r4[4];
                    ldmx4(r4, bbase + SMEM_SWIZZLE_128B(off));
                    bfr[pr * 2 + 0][0] = r4[0]; bfr[pr * 2 + 0][1] = r4[1];
                    bfr[pr * 2 + 1][0] = r4[2]; bfr[pr * 2 + 1][1] = r4[3];
                }
#pragma unroll
                for (int mi = 0; mi < 2; mi++)
#pragma unroll
                    for (int nb = 0; nb < 8; nb++)
                        mma_bf16(acc[mi][nb], afr[mi], bfr[nb]);
            }
        }
    }

    // Epilogue: bias + scale, split hi/lo bf16, scatter to [B,H,S,64].
    __nv_bfloat16* dsth = (z == 0) ? g_Qh : (z == 1) ? g_Kh : g_Vh;
    __nv_bfloat16* dstl = (z == 0) ? g_Ql : (z == 1) ? g_Kl : g_Vl;
    const float* bias = (z == 0) ? bq : (z == 1) ? bk : bv;
    const float scale = (z == 0) ? QSCALE : 1.0f;
    const int h = n_in_base >> 6;

#pragma unroll
    for (int mi = 0; mi < 2; mi++) {
#pragma unroll
        for (int half = 0; half < 2; half++) {
            int row = m0 + warp_m * 32 + mi * 16 + (lane >> 2) + half * 8;
            int b = row >> 11, s = row & 2047;
            size_t off = ((size_t)((b * NHEAD + h) * SEQ + s)) * HDIM;
#pragma unroll
            for (int nb = 0; nb < 8; nb++) {
                int d = nb * 8 + (lane & 3) * 2;
                float vx = (acc[mi][nb][half * 2 + 0] + bias[n_in_base + d + 0]) * scale;
                float vy = (acc[mi][nb][half * 2 + 1] + bias[n_in_base + d + 1]) * scale;
                __nv_bfloat16 hx = __float2bfloat16(vx);
                __nv_bfloat16 hy = __float2bfloat16(vy);
                __nv_bfloat16 lx = __float2bfloat16(vx - __bfloat162float(hx));
                __nv_bfloat16 ly = __float2bfloat16(vy - __bfloat162float(hy));
                *(__nv_bfloat162*)(dsth + off + d) = __halves2bfloat162(hx, hy);
                *(__nv_bfloat162*)(dstl + off + d) = __halves2bfloat162(lx, ly);
            }
        }
    }
}

// ---------------------------------------------------------------------------
// Flash attention via mma.sync bf16 hi/lo.
// CTA: 64 q rows x 1 head, 4 warps (warp = 16 q rows x full kv tile of 64).
// KV double-buffered via cp.async. Softmax in base-2 (scale folded into Q).
// grid (SEQ/64, NHEAD, BATCH), 128 threads.
// ---------------------------------------------------------------------------
#define ATTN_SMEM_BYTES (1024 + 81920)
#define NT (SEQ / 64)   // 32 kv tiles

__global__ __launch_bounds__(128)
void attn_mma_kernel(float* __restrict__ out)
{
    extern __shared__ __align__(16) char smem_raw[];
    char* sm = (char*)(((uintptr_t)smem_raw + 1023) & ~(uintptr_t)1023);
    const uint32_t sb = smem_u32(sm);

    const int tid = threadIdx.x, wid = tid >> 5, lane = tid & 31;
    const int q0 = blockIdx.x * 64, h = blockIdx.y, b = blockIdx.z;
    const size_t hb = (size_t)(b * NHEAD + h) * SEQ * HDIM;

    // smem regions (from aligned base):
    //  Qh 0 (8K), Ql 8192 (8K), KV buf0 @16384, buf1 @49152
    //  each KV buf: Kh +0, Kl +8192, Vh +16384, Vl +24576 (8K each)
    const uint32_t okv[2] = {16384u, 49152u};

    // ---- prefetch KV tile 0 (64 rows x 128B per array: 512 chunks of 16B) ----
    {
        const int kt = 0;
#pragma unroll
        for (int i = 0; i < 4; i++) {
            int idx = i * 128 + tid;
            int r = idx >> 3, c8 = (idx & 7) * 8;
            uint32_t so = SMEM_SWIZZLE_128B((uint32_t)(r * 128 + c8 * 2));
            size_t g = hb + (size_t)(kt + r) * HDIM + c8;
            cp_async16(sb + okv[0] + so,         g_Kh + g);
            cp_async16(sb + okv[0] + 8192 + so,  g_Kl + g);
            cp_async16(sb + okv[0] + 16384 + so, g_Vh + g);
            cp_async16(sb + okv[0] + 24576 + so, g_Vl + g);
        }
        asm volatile("cp.async.commit_group;" ::: "memory");
    }

    // ---- stage Q tile (64 rows) ----
#pragma unroll
    for (int i = 0; i < 4; i++) {
        int idx = i * 128 + tid;
        int r = idx >> 3, c8 = (idx & 7) * 8;
        uint32_t so = SMEM_SWIZZLE_128B((uint32_t)(r * 128 + c8 * 2));
        size_t g = hb + (size_t)(q0 + r) * HDIM + c8;
        *(uint4*)(sm + so)        = *(const uint4*)(g_Qh + g);
        *(uint4*)(sm + 8192 + so) = *(const uint4*)(g_Ql + g);
    }
    __syncthreads();

    // ---- persistent Q-hi fragments ----
    uint32_t aQh[4][4];
#pragma unroll
    for (int ks = 0; ks < 4; ks++) {
        uint32_t off = (uint32_t)((wid * 16 + (lane & 15)) * 128 + ks * 32 + (lane >> 4) * 16);
        ldmx4(aQh[ks], sb + SMEM_SWIZZLE_128B(off));
    }

    float outw[8][4];
#pragma unroll
    for (int nb = 0; nb < 8; nb++)
#pragma unroll
        for (int q = 0; q < 4; q++) outw[nb][q] = 0.f;
    float m0 = -CUDART_INF_F, m1 = -CUDART_INF_F, l0 = 0.f, l1 = 0.f;

    for (int t = 0; t < NT; t++) {
        // prefetch t+1
        if (t + 1 < NT) {
            const int kt = (t + 1) * 64;
            const uint32_t ob = okv[(t + 1) & 1];
#pragma unroll
            for (int i = 0; i < 4; i++) {
                int idx = i * 128 + tid;
                int r = idx >> 3, c8 = (idx & 7) * 8;
                uint32_t so = SMEM_SWIZZLE_128B((uint32_t)(r * 128 + c8 * 2));
                size_t g = hb + (size_t)(kt + r) * HDIM + c8;
                cp_async16(sb + ob + so,         g_Kh + g);
                cp_async16(sb + ob + 8192 + so,  g_Kl + g);
                cp_async16(sb + ob + 16384 + so, g_Vh + g);
                cp_async16(sb + ob + 24576 + so, g_Vl + g);
            }
            asm volatile("cp.async.commit_group;" ::: "memory");
            asm volatile("cp.async.wait_group 1;" ::: "memory");
        } else {
            asm volatile("cp.async.wait_group 0;" ::: "memory");
        }
        __syncthreads();

        const uint32_t kb = okv[t & 1];

        // ---- QK^T: warp computes 16x64 scores, 3-pass hi/lo ----
        float sc[8][4];
#pragma unroll
        for (int nb = 0; nb < 8; nb++)
#pragma unroll
            for (int q = 0; q < 4; q++) sc[nb][q] = 0.f;

#pragma unroll
        for (int ks = 0; ks < 4; ks++) {
            uint32_t bh[8][2], bl[8][2], aql[4];
#pragma unroll
            for (int pr = 0; pr < 4; pr++) {
                uint32_t row = (uint32_t)(pr * 16 + (lane & 7) + ((lane >> 4) << 3));
                uint32_t off = row * 128 + ks * 32 + (((lane >> 3) & 1) << 4);
                uint32_t r4[4];
                ldmx4(r4, sb + kb + SMEM_SWIZZLE_128B(off));
                bh[pr * 2 + 0][0] = r4[0]; bh[pr * 2 + 0][1] = r4[1];
                bh[pr * 2 + 1][0] = r4[2]; bh[pr * 2 + 1][1] = r4[3];
            }
            {
                uint32_t off = (uint32_t)((wid * 16 + (lane & 15)) * 128 + ks * 32 + (lane >> 4) * 16);
                ldmx4(aql, sb + 8192 + SMEM_SWIZZLE_128B(off));
            }
#pragma unroll
            for (int nb = 0; nb < 8; nb++) mma_bf16(sc[nb], aQh[ks], bh[nb]);
#pragma unroll
            for (int nb = 0; nb < 8; nb++) mma_bf16(sc[nb], aql, bh[nb]);
#pragma unroll
            for (int pr = 0; pr < 4; pr++) {
                uint32_t row = (uint32_t)(pr * 16 + (lane & 7) + ((lane >> 4) << 3));
                uint32_t off = row * 128 + ks * 32 + (((lane >> 3) & 1) << 4);
                uint32_t r4[4];
                ldmx4(r4, sb + kb + 8192 + SMEM_SWIZZLE_128B(off));
                bl[pr * 2 + 0][0] = r4[0]; bl[pr * 2 + 0][1] = r4[1];
                bl[pr * 2 + 1][0] = r4[2]; bl[pr * 2 + 1][1] = r4[3];
            }
#pragma unroll
            for (int nb = 0; nb < 8; nb++) mma_bf16(sc[nb], aQh[ks], bl[nb]);
        }

        // ---- online softmax (base-2) ----
        float mx0 = -CUDART_INF_F, mx1 = -CUDART_INF_F;
#pragma unroll
        for (int nb = 0; nb < 8; nb++) {
            mx0 = fmaxf(mx0, fmaxf(sc[nb][0], sc[nb][1]));
            mx1 = fmaxf(mx1, fmaxf(sc[nb][2], sc[nb][3]));
        }
        mx0 = fmaxf(mx0, __shfl_xor_sync(0xffffffffu, mx0, 1));
        mx0 = fmaxf(mx0, __shfl_xor_sync(0xffffffffu, mx0, 2));
        mx1 = fmaxf(mx1, __shfl_xor_sync(0xffffffffu, mx1, 1));
        mx1 = fmaxf(mx1, __shfl_xor_sync(0xffffffffu, mx1, 2));
        float mn0 = fmaxf(m0, mx0), mn1 = fmaxf(m1, mx1);
        float c0 = exp2f(m0 - mn0), c1 = exp2f(m1 - mn1);
        m0 = mn0; m1 = mn1;
        float s0 = 0.f, s1 = 0.f;
#pragma unroll
        for (int nb = 0; nb < 8; nb++) {
            sc[nb][0] = exp2f(sc[nb][0] - mn0); s0 += sc[nb][0];
            sc[nb][1] = exp2f(sc[nb][1] - mn0); s0 += sc[nb][1];
            sc[nb][2] = exp2f(sc[nb][2] - mn1); s1 += sc[nb][2];
            sc[nb][3] = exp2f(sc[nb][3] - mn1); s1 += sc[nb][3];
        }
        l0 = l0 * c0 + s0;
        l1 = l1 * c1 + s1;
#pragma unroll
        for (int nb = 0; nb < 8; nb++) {
            outw[nb][0] *= c0; outw[nb][1] *= c0;
            outw[nb][2] *= c1; outw[nb][3] *= c1;
        }

        // ---- P @ V: P hi/lo in registers, V hi/lo via ldmatrix.trans ----
#pragma unroll
        for (int kc = 0; kc < 4; kc++) {
            uint32_t aPh[4], aPl[4];
            {
                float* f0 = sc[2 * kc];
                float* f1 = sc[2 * kc + 1];
                aPh[0] = pack_bf16(f0[0], f0[1]);
                aPh[1] = pack_bf16(f0[2], f0[3]);
                aPh[2] = pack_bf16(f1[0], f1[1]);
                aPh[3] = pack_bf16(f1[2], f1[3]);
#pragma unroll
                for (int q = 0; q < 4; q++) {
                    float* f = (q < 2) ? f0 : f1;
                    int j = (q & 1) * 2;
                    __nv_bfloat162 hh = *(__nv_bfloat162*)&aPh[q];
                    float rx = f[j + 0] - __bfloat162float(hh.x);
                    float ry = f[j + 1] - __bfloat162float(hh.y);
                    aPl[q] = pack_bf16(rx, ry);
                }
            }
            uint32_t bvh[8][2], bvl[8][2];
#pragma unroll
            for (int pn = 0; pn < 4; pn++) {
                uint32_t grp = (uint32_t)(lane >> 3);
                uint32_t row = (uint32_t)(kc * 16 + (grp & 1) * 8 + (lane & 7));
                uint32_t col = (uint32_t)(pn * 16 + (grp >> 1) * 8);
                uint32_t off = row * 128 + col * 2;
                uint32_t r4[4];
                ldmx4t(r4, sb + kb + 16384 + SMEM_SWIZZLE_128B(off));
                bvh[pn * 2 + 0][0] = r4[0]; bvh[pn * 2 + 0][1] = r4[1];
                bvh[pn * 2 + 1][0] = r4[2]; bvh[pn * 2 + 1][1] = r4[3];
                ldmx4t(r4, sb + kb + 24576 + SMEM_SWIZZLE_128B(off));
                bvl[pn * 2 + 0][0] = r4[0]; bvl[pn * 2 + 0][1] = r4[1];
                bvl[pn * 2 + 1][0] = r4[2]; bvl[pn * 2 + 1][1] = r4[3];
            }
#pragma unroll
            for (int nb = 0; nb < 8; nb++) mma_bf16(outw[nb], aPh, bvh[nb]);
#pragma unroll
            for (int nb = 0; nb < 8; nb++) mma_bf16(outw[nb], aPl, bvh[nb]);
#pragma unroll
            for (int nb = 0; nb < 8; nb++) mma_bf16(outw[nb], aPh, bvl[nb]);
        }
        __syncthreads();   // all warps done reading this KV buf before overwrite
    }

    // ---- finalize: reduce l across quad, divide, write ----
    l0 += __shfl_xor_sync(0xffffffffu, l0, 1);
    l0 += __shfl_xor_sync(0xffffffffu, l0, 2);
    l1 += __shfl_xor_sync(0xffffffffu, l1, 1);
    l1 += __shfl_xor_sync(0xffffffffu, l1, 2);
    float inv0 = 1.0f / l0, inv1 = 1.0f / l1;

    const int s0r = q0 + wid * 16 + (lane >> 2);
    const int s1r = s0r + 8;
    float* o0 = out + ((size_t)(b * SEQ + s0r)) * DMODEL + h * HDIM;
    float* o1 = out + ((size_t)(b * SEQ + s1r)) * DMODEL + h * HDIM;
#pragma unroll
    for (int nb = 0; nb < 8; nb++) {
        int d = nb * 8 + (lane & 3) * 2;
        float2 v0; v0.x = outw[nb][0] * inv0; v0.y = outw[nb][1] * inv0;
        float2 v1; v1.x = outw[nb][2] * inv1; v1.y = outw[nb][3] * inv1;
        *(float2*)(o0 + d) = v0;
        *(float2*)(o1 + d) = v1;
    }
}

// ---------------------------------------------------------------------------
extern "C" void kernel_launch(void* const* d_in, const int* in_sizes, int n_in,
                              void* d_out, int out_size)
{
    const float* X  = (const float*)d_in[0];
    const float* Wq = (const float*)d_in[1];
    const float* bq = (const float*)d_in[2];
    const float* Wk = (const float*)d_in[3];
    const float* bk = (const float*)d_in[4];
    const float* Wv = (const float*)d_in[5];
    const float* bv = (const float*)d_in[6];
    float* out = (float*)d_out;

    cudaFuncSetAttribute(proj_mma_kernel,
                         cudaFuncAttributeMaxDynamicSharedMemorySize, PROJ_SMEM_BYTES);
    cudaFuncSetAttribute(attn_mma_kernel,
                         cudaFuncAttributeMaxDynamicSharedMemorySize, ATTN_SMEM_BYTES);

    convert_x_kernel<<<MROWS * DMODEL / 1024, 256>>>(X);
    convert_w_kernel<<<dim3(DMODEL * DMODEL / 1024, 3), 256>>>(Wq, Wk, Wv);
    proj_mma_kernel<<<dim3(MROWS / 128, 3 * DMODEL / 128), 256, PROJ_SMEM_BYTES>>>(bq, bk, bv);
    attn_mma_kernel<<<dim3(SEQ / 64, NHEAD, BATCH), 128, ATTN_SMEM_BYTES>>>(out);
}

// round 8
// speedup vs baseline: 4.9765x; 1.5477x over previous
#include <cuda_runtime.h>
#include <cuda_bf16.h>
#include <math_constants.h>
#include <cstdint>

#define BATCH  4
#define SEQ    2048
#define DMODEL 1024
#define NHEAD  16
#define HDIM   64
#define MROWS  (BATCH * SEQ)   // 8192

// Q scale folds 1/sqrt(64) and log2(e):  0.125 * 1.4426950408889634
#define QSCALE 0.18033688f

// ---------------------------------------------------------------------------
// Scratch (bf16 hi/lo everywhere)
// ---------------------------------------------------------------------------
__device__ __nv_bfloat16 g_Xh[(size_t)MROWS * DMODEL];
__device__ __nv_bfloat16 g_Xl[(size_t)MROWS * DMODEL];
__device__ __nv_bfloat16 g_Wh[(size_t)3 * DMODEL * DMODEL];
__device__ __nv_bfloat16 g_Wl[(size_t)3 * DMODEL * DMODEL];

__device__ __nv_bfloat16 g_Qh[(size_t)MROWS * HDIM * NHEAD];
__device__ __nv_bfloat16 g_Ql[(size_t)MROWS * HDIM * NHEAD];
__device__ __nv_bfloat16 g_Kh[(size_t)MROWS * HDIM * NHEAD];
__device__ __nv_bfloat16 g_Kl[(size_t)MROWS * HDIM * NHEAD];
__device__ __nv_bfloat16 g_Vh[(size_t)MROWS * HDIM * NHEAD];
__device__ __nv_bfloat16 g_Vl[(size_t)MROWS * HDIM * NHEAD];

#define SMEM_SWIZZLE_128B(o) ((o) ^ (((o) >> 3) & 0x70))

__device__ __forceinline__ uint32_t smem_u32(const void* p) {
    uint32_t a;
    asm("{ .reg .u64 t; cvta.to.shared.u64 t, %1; cvt.u32.u64 %0, t; }" : "=r"(a) : "l"(p));
    return a;
}

__device__ __forceinline__ void ldmx4(uint32_t* r, uint32_t addr) {
    asm volatile("ldmatrix.sync.aligned.m8n8.x4.shared.b16 {%0,%1,%2,%3}, [%4];"
                 : "=r"(r[0]), "=r"(r[1]), "=r"(r[2]), "=r"(r[3]) : "r"(addr));
}
__device__ __forceinline__ void ldmx4t(uint32_t* r, uint32_t addr) {
    asm volatile("ldmatrix.sync.aligned.m8n8.x4.trans.shared.b16 {%0,%1,%2,%3}, [%4];"
                 : "=r"(r[0]), "=r"(r[1]), "=r"(r[2]), "=r"(r[3]) : "r"(addr));
}

__device__ __forceinline__ void mma_bf16(float* c, const uint32_t* a, const uint32_t* b) {
    asm volatile(
        "mma.sync.aligned.m16n8k16.row.col.f32.bf16.bf16.f32 "
        "{%0,%1,%2,%3}, {%4,%5,%6,%7}, {%8,%9}, {%0,%1,%2,%3};"
        : "+f"(c[0]), "+f"(c[1]), "+f"(c[2]), "+f"(c[3])
        : "r"(a[0]), "r"(a[1]), "r"(a[2]), "r"(a[3]), "r"(b[0]), "r"(b[1]));
}

__device__ __forceinline__ uint32_t pack_bf16(float lo, float hi) {
    uint32_t d;
    asm("cvt.rn.bf16x2.f32 %0, %1, %2;" : "=r"(d) : "f"(hi), "f"(lo));
    return d;
}

__device__ __forceinline__ void cp_async16(uint32_t saddr, const void* gaddr) {
    asm volatile("cp.async.cg.shared.global [%0], [%1], 16;" :: "r"(saddr), "l"(gaddr));
}

// ---------------------------------------------------------------------------
// fp32 -> bf16 hi/lo split converters
// ---------------------------------------------------------------------------
__global__ __launch_bounds__(256)
void convert_x_kernel(const float* __restrict__ X)
{
    size_t i = ((size_t)blockIdx.x * 256 + threadIdx.x) * 4;
    float4 v = *(const float4*)(X + i);
    __nv_bfloat16 h0 = __float2bfloat16(v.x);
    __nv_bfloat16 h1 = __float2bfloat16(v.y);
    __nv_bfloat16 h2 = __float2bfloat16(v.z);
    __nv_bfloat16 h3 = __float2bfloat16(v.w);
    __nv_bfloat16 l0 = __float2bfloat16(v.x - __bfloat162float(h0));
    __nv_bfloat16 l1 = __float2bfloat16(v.y - __bfloat162float(h1));
    __nv_bfloat16 l2 = __float2bfloat16(v.z - __bfloat162float(h2));
    __nv_bfloat16 l3 = __float2bfloat16(v.w - __bfloat162float(h3));
    __nv_bfloat162* ph = (__nv_bfloat162*)(g_Xh + i);
    __nv_bfloat162* pl = (__nv_bfloat162*)(g_Xl + i);
    ph[0] = __halves2bfloat162(h0, h1); ph[1] = __halves2bfloat162(h2, h3);
    pl[0] = __halves2bfloat162(l0, l1); pl[1] = __halves2bfloat162(l2, l3);
}

__global__ __launch_bounds__(256)
void convert_w_kernel(const float* __restrict__ Wq,
                      const float* __restrict__ Wk,
                      const float* __restrict__ Wv)
{
    int z = blockIdx.y;
    const float* W = (z == 0) ? Wq : (z == 1) ? Wk : Wv;
    size_t i = ((size_t)blockIdx.x * 256 + threadIdx.x) * 4;
    float4 v = *(const float4*)(W + i);
    size_t o = (size_t)z * DMODEL * DMODEL + i;
    __nv_bfloat16 h0 = __float2bfloat16(v.x);
    __nv_bfloat16 h1 = __float2bfloat16(v.y);
    __nv_bfloat16 h2 = __float2bfloat16(v.z);
    __nv_bfloat16 h3 = __float2bfloat16(v.w);
    __nv_bfloat16 l0 = __float2bfloat16(v.x - __bfloat162float(h0));
    __nv_bfloat16 l1 = __float2bfloat16(v.y - __bfloat162float(h1));
    __nv_bfloat16 l2 = __float2bfloat16(v.z - __bfloat162float(h2));
    __nv_bfloat16 l3 = __float2bfloat16(v.w - __bfloat162float(h3));
    __nv_bfloat162* ph = (__nv_bfloat162*)(g_Wh + o);
    __nv_bfloat162* pl = (__nv_bfloat162*)(g_Wl + o);
    ph[0] = __halves2bfloat162(h0, h1); ph[1] = __halves2bfloat162(h2, h3);
    pl[0] = __halves2bfloat162(l0, l1); pl[1] = __halves2bfloat162(l2, l3);
}

// ---------------------------------------------------------------------------
// Projection GEMM via mma.sync bf16 (hi/lo split, fp32 accum).
// C[8192, 3072] = X * [Wq|Wk|Wv]^T.  CTA tile 128x128, warp tile 32x64.
// cp.async double-buffered K-chunks (64). Epilogue writes bf16 hi/lo Q/K/V.
// ---------------------------------------------------------------------------
#define PROJ_SMEM_BYTES (1024 + 2 * 65536)

__global__ __launch_bounds__(256, 1)
void proj_mma_kernel(const float* __restrict__ bq,
                     const float* __restrict__ bk,
                     const float* __restrict__ bv)
{
    extern __shared__ __align__(16) char smem_raw[];
    char* tile = (char*)(((uintptr_t)smem_raw + 1023) & ~(uintptr_t)1023);
    const uint32_t sbase = smem_u32(tile);
    // stage layout (per 64KB stage): Ah +0, Al +16K, Bh +32K, Bl +48K

    const int tid  = threadIdx.x;
    const int wid  = tid >> 5;
    const int lane = tid & 31;
    const int warp_m = wid & 3;
    const int warp_n = wid >> 2;

    const int m0 = blockIdx.x * 128;
    const int n0 = blockIdx.y * 128;
    const int z  = n0 >> 10;
    const int n_in_base = (n0 & 1023) + warp_n * 64;

    float acc[2][8][4];
#pragma unroll
    for (int mi = 0; mi < 2; mi++)
#pragma unroll
        for (int nb = 0; nb < 8; nb++)
#pragma unroll
            for (int q = 0; q < 4; q++) acc[mi][nb][q] = 0.f;

#define PROJ_PREFETCH(KC, STG) do {                                               \
    const int _k0 = (KC) * 64;                                                    \
    const uint32_t _ob = sbase + (uint32_t)(STG) * 65536u;                        \
    _Pragma("unroll")                                                             \
    for (int _i = 0; _i < 4; _i++) {                                              \
        int _idx = _i * 256 + tid;                                                \
        int _r = _idx >> 3, _c8 = (_idx & 7) * 8;                                 \
        uint32_t _so = SMEM_SWIZZLE_128B((uint32_t)(_r * 128 + _c8 * 2));         \
        size_t _ga = (size_t)(m0 + _r) * DMODEL + _k0 + _c8;                      \
        size_t _gb = (size_t)(n0 + _r) * DMODEL + _k0 + _c8;                      \
        cp_async16(_ob + _so,          g_Xh + _ga);                               \
        cp_async16(_ob + 16384u + _so, g_Xl + _ga);                               \
        cp_async16(_ob + 32768u + _so, g_Wh + _gb);                               \
        cp_async16(_ob + 49152u + _so, g_Wl + _gb);                               \
    }                                                                             \
    asm volatile("cp.async.commit_group;" ::: "memory");                          \
} while (0)

    PROJ_PREFETCH(0, 0);

    for (int kc = 0; kc < 16; kc++) {
        if (kc + 1 < 16) {
            PROJ_PREFETCH(kc + 1, (kc + 1) & 1);
            asm volatile("cp.async.wait_group 1;" ::: "memory");
        } else {
            asm volatile("cp.async.wait_group 0;" ::: "memory");
        }
        __syncthreads();

        const uint32_t stg = sbase + (uint32_t)(kc & 1) * 65536u;

#pragma unroll
        for (int pass = 0; pass < 3; pass++) {
            const uint32_t abase = stg + ((pass == 2) ? 16384u : 0u);
            const uint32_t bbase = stg + 32768u + ((pass == 1) ? 16384u : 0u);
#pragma unroll
            for (int ks = 0; ks < 4; ks++) {
                uint32_t afr[2][4];
#pragma unroll
                for (int mi = 0; mi < 2; mi++) {
                    uint32_t off = (uint32_t)((warp_m * 32 + mi * 16 + (lane & 15)) * 128
                                              + ks * 32 + (lane >> 4) * 16);
                    ldmx4(afr[mi], abase + SMEM_SWIZZLE_128B(off));
                }
                uint32_t bfr[8][2];
#pragma unroll
                for (int pr = 0; pr < 4; pr++) {
                    uint32_t row = (uint32_t)(warp_n * 64 + pr * 16 + (lane & 7) + ((lane >> 4) << 3));
                    uint32_t off = row * 128 + ks * 32 + (((lane >> 3) & 1) << 4);
                    uint32_t r4[4];
                    ldmx4(r4, bbase + SMEM_SWIZZLE_128B(off));
                    bfr[pr * 2 + 0][0] = r4[0]; bfr[pr * 2 + 0][1] = r4[1];
                    bfr[pr * 2 + 1][0] = r4[2]; bfr[pr * 2 + 1][1] = r4[3];
                }
#pragma unroll
                for (int mi = 0; mi < 2; mi++)
#pragma unroll
                    for (int nb = 0; nb < 8; nb++)
                        mma_bf16(acc[mi][nb], afr[mi], bfr[nb]);
            }
        }
        if (kc + 1 < 16) __syncthreads();  // readers done before next prefetch overwrites
    }

    // Epilogue: bias + scale, split hi/lo bf16, scatter to [B,H,S,64].
    __nv_bfloat16* dsth = (z == 0) ? g_Qh : (z == 1) ? g_Kh : g_Vh;
    __nv_bfloat16* dstl = (z == 0) ? g_Ql : (z == 1) ? g_Kl : g_Vl;
    const float* bias = (z == 0) ? bq : (z == 1) ? bk : bv;
    const float scale = (z == 0) ? QSCALE : 1.0f;
    const int h = n_in_base >> 6;

#pragma unroll
    for (int mi = 0; mi < 2; mi++) {
#pragma unroll
        for (int half = 0; half < 2; half++) {
            int row = m0 + warp_m * 32 + mi * 16 + (lane >> 2) + half * 8;
            int b = row >> 11, s = row & 2047;
            size_t off = ((size_t)((b * NHEAD + h) * SEQ + s)) * HDIM;
#pragma unroll
            for (int nb = 0; nb < 8; nb++) {
                int d = nb * 8 + (lane & 3) * 2;
                float vx = (acc[mi][nb][half * 2 + 0] + bias[n_in_base + d + 0]) * scale;
                float vy = (acc[mi][nb][half * 2 + 1] + bias[n_in_base + d + 1]) * scale;
                __nv_bfloat16 hx = __float2bfloat16(vx);
                __nv_bfloat16 hy = __float2bfloat16(vy);
                __nv_bfloat16 lx = __float2bfloat16(vx - __bfloat162float(hx));
                __nv_bfloat16 ly = __float2bfloat16(vy - __bfloat162float(hy));
                *(__nv_bfloat162*)(dsth + off + d) = __halves2bfloat162(hx, hy);
                *(__nv_bfloat162*)(dstl + off + d) = __halves2bfloat162(lx, ly);
            }
        }
    }
}

// ---------------------------------------------------------------------------
// Flash attention via mma.sync bf16 hi/lo (R5-passing version: 3-pass QK^T,
// 3-pass P@V including Pl·Vh).
// CTA: 64 q rows x 1 head, 4 warps. KV double-buffered via cp.async.
// grid (SEQ/64, NHEAD, BATCH), 128 threads.
// ---------------------------------------------------------------------------
#define ATTN_SMEM_BYTES (1024 + 81920)
#define NT (SEQ / 64)   // 32 kv tiles

__global__ __launch_bounds__(128)
void attn_mma_kernel(float* __restrict__ out)
{
    extern __shared__ __align__(16) char smem_raw[];
    char* sm = (char*)(((uintptr_t)smem_raw + 1023) & ~(uintptr_t)1023);
    const uint32_t sb = smem_u32(sm);

    const int tid = threadIdx.x, wid = tid >> 5, lane = tid & 31;
    const int q0 = blockIdx.x * 64, h = blockIdx.y, b = blockIdx.z;
    const size_t hb = (size_t)(b * NHEAD + h) * SEQ * HDIM;

    // smem: Qh 0 (8K), Ql 8192 (8K), KV buf0 @16384, buf1 @49152
    //  each KV buf: Kh +0, Kl +8192, Vh +16384, Vl +24576 (8K each)
    const uint32_t okv[2] = {16384u, 49152u};

    // ---- prefetch KV tile 0 (512 x 16B chunks per array) ----
    {
        const int kt = 0;
#pragma unroll
        for (int i = 0; i < 4; i++) {
            int idx = i * 128 + tid;
            int r = idx >> 3, c8 = (idx & 7) * 8;
            uint32_t so = SMEM_SWIZZLE_128B((uint32_t)(r * 128 + c8 * 2));
            size_t g = hb + (size_t)(kt + r) * HDIM + c8;
            cp_async16(sb + okv[0] + so,         g_Kh + g);
            cp_async16(sb + okv[0] + 8192 + so,  g_Kl + g);
            cp_async16(sb + okv[0] + 16384 + so, g_Vh + g);
            cp_async16(sb + okv[0] + 24576 + so, g_Vl + g);
        }
        asm volatile("cp.async.commit_group;" ::: "memory");
    }

    // ---- stage Q tile (64 rows) ----
#pragma unroll
    for (int i = 0; i < 4; i++) {
        int idx = i * 128 + tid;
        int r = idx >> 3, c8 = (idx & 7) * 8;
        uint32_t so = SMEM_SWIZZLE_128B((uint32_t)(r * 128 + c8 * 2));
        size_t g = hb + (size_t)(q0 + r) * HDIM + c8;
        *(uint4*)(sm + so)        = *(const uint4*)(g_Qh + g);
        *(uint4*)(sm + 8192 + so) = *(const uint4*)(g_Ql + g);
    }
    __syncthreads();

    // ---- persistent Q-hi fragments ----
    uint32_t aQh[4][4];
#pragma unroll
    for (int ks = 0; ks < 4; ks++) {
        uint32_t off = (uint32_t)((wid * 16 + (lane & 15)) * 128 + ks * 32 + (lane >> 4) * 16);
        ldmx4(aQh[ks], sb + SMEM_SWIZZLE_128B(off));
    }

    float outw[8][4];
#pragma unroll
    for (int nb = 0; nb < 8; nb++)
#pragma unroll
        for (int q = 0; q < 4; q++) outw[nb][q] = 0.f;
    float m0 = -CUDART_INF_F, m1 = -CUDART_INF_F, l0 = 0.f, l1 = 0.f;

    for (int t = 0; t < NT; t++) {
        // prefetch t+1
        if (t + 1 < NT) {
            const int kt = (t + 1) * 64;
            const uint32_t ob = okv[(t + 1) & 1];
#pragma unroll
            for (int i = 0; i < 4; i++) {
                int idx = i * 128 + tid;
                int r = idx >> 3, c8 = (idx & 7) * 8;
                uint32_t so = SMEM_SWIZZLE_128B((uint32_t)(r * 128 + c8 * 2));
                size_t g = hb + (size_t)(kt + r) * HDIM + c8;
                cp_async16(sb + ob + so,         g_Kh + g);
                cp_async16(sb + ob + 8192 + so,  g_Kl + g);
                cp_async16(sb + ob + 16384 + so, g_Vh + g);
                cp_async16(sb + ob + 24576 + so, g_Vl + g);
            }
            asm volatile("cp.async.commit_group;" ::: "memory");
            asm volatile("cp.async.wait_group 1;" ::: "memory");
        } else {
            asm volatile("cp.async.wait_group 0;" ::: "memory");
        }
        __syncthreads();

        const uint32_t kb = okv[t & 1];

        // ---- QK^T: warp computes 16x64 scores, 3-pass hi/lo ----
        float sc[8][4];
#pragma unroll
        for (int nb = 0; nb < 8; nb++)
#pragma unroll
            for (int q = 0; q < 4; q++) sc[nb][q] = 0.f;

#pragma unroll
        for (int ks = 0; ks < 4; ks++) {
            uint32_t bh[8][2], bl[8][2], aql[4];
#pragma unroll
            for (int pr = 0; pr < 4; pr++) {
                uint32_t row = (uint32_t)(pr * 16 + (lane & 7) + ((lane >> 4) << 3));
                uint32_t off = row * 128 + ks * 32 + (((lane >> 3) & 1) << 4);
                uint32_t r4[4];
                ldmx4(r4, sb + kb + SMEM_SWIZZLE_128B(off));
                bh[pr * 2 + 0][0] = r4[0]; bh[pr * 2 + 0][1] = r4[1];
                bh[pr * 2 + 1][0] = r4[2]; bh[pr * 2 + 1][1] = r4[3];
            }
            {
                uint32_t off = (uint32_t)((wid * 16 + (lane & 15)) * 128 + ks * 32 + (lane >> 4) * 16);
                ldmx4(aql, sb + 8192 + SMEM_SWIZZLE_128B(off));
            }
#pragma unroll
            for (int nb = 0; nb < 8; nb++) mma_bf16(sc[nb], aQh[ks], bh[nb]);
#pragma unroll
            for (int nb = 0; nb < 8; nb++) mma_bf16(sc[nb], aql, bh[nb]);
#pragma unroll
            for (int pr = 0; pr < 4; pr++) {
                uint32_t row = (uint32_t)(pr * 16 + (lane & 7) + ((lane >> 4) << 3));
                uint32_t off = row * 128 + ks * 32 + (((lane >> 3) & 1) << 4);
                uint32_t r4[4];
                ldmx4(r4, sb + kb + 8192 + SMEM_SWIZZLE_128B(off));
                bl[pr * 2 + 0][0] = r4[0]; bl[pr * 2 + 0][1] = r4[1];
                bl[pr * 2 + 1][0] = r4[2]; bl[pr * 2 + 1][1] = r4[3];
            }
#pragma unroll
            for (int nb = 0; nb < 8; nb++) mma_bf16(sc[nb], aQh[ks], bl[nb]);
        }

        // ---- online softmax (base-2) ----
        float mx0 = -CUDART_INF_F, mx1 = -CUDART_INF_F;
#pragma unroll
        for (int nb = 0; nb < 8; nb++) {
            mx0 = fmaxf(mx0, fmaxf(sc[nb][0], sc[nb][1]));
            mx1 = fmaxf(mx1, fmaxf(sc[nb][2], sc[nb][3]));
        }
        mx0 = fmaxf(mx0, __shfl_xor_sync(0xffffffffu, mx0, 1));
        mx0 = fmaxf(mx0, __shfl_xor_sync(0xffffffffu, mx0, 2));
        mx1 = fmaxf(mx1, __shfl_xor_sync(0xffffffffu, mx1, 1));
        mx1 = fmaxf(mx1, __shfl_xor_sync(0xffffffffu, mx1, 2));
        float mn0 = fmaxf(m0, mx0), mn1 = fmaxf(m1, mx1);
        float c0 = exp2f(m0 - mn0), c1 = exp2f(m1 - mn1);
        m0 = mn0; m1 = mn1;
        float s0 = 0.f, s1 = 0.f;
#pragma unroll
        for (int nb = 0; nb < 8; nb++) {
            sc[nb][0] = exp2f(sc[nb][0] - mn0); s0 += sc[nb][0];
            sc[nb][1] = exp2f(sc[nb][1] - mn0); s0 += sc[nb][1];
            sc[nb][2] = exp2f(sc[nb][2] - mn1); s1 += sc[nb][2];
            sc[nb][3] = exp2f(sc[nb][3] - mn1); s1 += sc[nb][3];
        }
        l0 = l0 * c0 + s0;
        l1 = l1 * c1 + s1;
#pragma unroll
        for (int nb = 0; nb < 8; nb++) {
            outw[nb][0] *= c0; outw[nb][1] *= c0;
            outw[nb][2] *= c1; outw[nb][3] *= c1;
        }

        // ---- P @ V: P hi/lo in registers, V hi/lo via ldmatrix.trans (3-pass) ----
#pragma unroll
        for (int kc = 0; kc < 4; kc++) {
            uint32_t aPh[4], aPl[4];
            {
                float* f0 = sc[2 * kc];
                float* f1 = sc[2 * kc + 1];
                aPh[0] = pack_bf16(f0[0], f0[1]);
                aPh[1] = pack_bf16(f0[2], f0[3]);
                aPh[2] = pack_bf16(f1[0], f1[1]);
                aPh[3] = pack_bf16(f1[2], f1[3]);
#pragma unroll
                for (int q = 0; q < 4; q++) {
                    float* f = (q < 2) ? f0 : f1;
                    int j = (q & 1) * 2;
                    __nv_bfloat162 hh = *(__nv_bfloat162*)&aPh[q];
                    float rx = f[j + 0] - __bfloat162float(hh.x);
                    float ry = f[j + 1] - __bfloat162float(hh.y);
                    aPl[q] = pack_bf16(rx, ry);
                }
            }
            uint32_t bvh[8][2], bvl[8][2];
#pragma unroll
            for (int pn = 0; pn < 4; pn++) {
                uint32_t grp = (uint32_t)(lane >> 3);
                uint32_t row = (uint32_t)(kc * 16 + (grp & 1) * 8 + (lane & 7));
                uint32_t col = (uint32_t)(pn * 16 + (grp >> 1) * 8);
                uint32_t off = row * 128 + col * 2;
                uint32_t r4[4];
                ldmx4t(r4, sb + kb + 16384 + SMEM_SWIZZLE_128B(off));
                bvh[pn * 2 + 0][0] = r4[0]; bvh[pn * 2 + 0][1] = r4[1];
                bvh[pn * 2 + 1][0] = r4[2]; bvh[pn * 2 + 1][1] = r4[3];
                ldmx4t(r4, sb + kb + 24576 + SMEM_SWIZZLE_128B(off));
                bvl[pn * 2 + 0][0] = r4[0]; bvl[pn * 2 + 0][1] = r4[1];
                bvl[pn * 2 + 1][0] = r4[2]; bvl[pn * 2 + 1][1] = r4[3];
            }
#pragma unroll
            for (int nb = 0; nb < 8; nb++) mma_bf16(outw[nb], aPh, bvh[nb]);
#pragma unroll
            for (int nb = 0; nb < 8; nb++) mma_bf16(outw[nb], aPl, bvh[nb]);
#pragma unroll
            for (int nb = 0; nb < 8; nb++) mma_bf16(outw[nb], aPh, bvl[nb]);
        }
        __syncthreads();   // all warps done reading this KV buf before overwrite
    }

    // ---- finalize: reduce l across quad, divide, write ----
    l0 += __shfl_xor_sync(0xffffffffu, l0, 1);
    l0 += __shfl_xor_sync(0xffffffffu, l0, 2);
    l1 += __shfl_xor_sync(0xffffffffu, l1, 1);
    l1 += __shfl_xor_sync(0xffffffffu, l1, 2);
    float inv0 = 1.0f / l0, inv1 = 1.0f / l1;

    const int s0r = q0 + wid * 16 + (lane >> 2);
    const int s1r = s0r + 8;
    float* o0 = out + ((size_t)(b * SEQ + s0r)) * DMODEL + h * HDIM;
    float* o1 = out + ((size_t)(b * SEQ + s1r)) * DMODEL + h * HDIM;
#pragma unroll
    for (int nb = 0; nb < 8; nb++) {
        int d = nb * 8 + (lane & 3) * 2;
        float2 v0; v0.x = outw[nb][0] * inv0; v0.y = outw[nb][1] * inv0;
        float2 v1; v1.x = outw[nb][2] * inv1; v1.y = outw[nb][3] * inv1;
        *(float2*)(o0 + d) = v0;
        *(float2*)(o1 + d) = v1;
    }
}

// ---------------------------------------------------------------------------
extern "C" void kernel_launch(void* const* d_in, const int* in_sizes, int n_in,
                              void* d_out, int out_size)
{
    const float* X  = (const float*)d_in[0];
    const float* Wq = (const float*)d_in[1];
    const float* bq = (const float*)d_in[2];
    const float* Wk = (const float*)d_in[3];
    const float* bk = (const float*)d_in[4];
    const float* Wv = (const float*)d_in[5];
    const float* bv = (const float*)d_in[6];
    float* out = (float*)d_out;

    cudaFuncSetAttribute(proj_mma_kernel,
                         cudaFuncAttributeMaxDynamicSharedMemorySize, PROJ_SMEM_BYTES);
    cudaFuncSetAttribute(attn_mma_kernel,
                         cudaFuncAttributeMaxDynamicSharedMemorySize, ATTN_SMEM_BYTES);

    convert_x_kernel<<<MROWS * DMODEL / 1024, 256>>>(X);
    convert_w_kernel<<<dim3(DMODEL * DMODEL / 1024, 3), 256>>>(Wq, Wk, Wv);
    proj_mma_kernel<<<dim3(MROWS / 128, 3 * DMODEL / 128), 256, PROJ_SMEM_BYTES>>>(bq, bk, bv);
    attn_mma_kernel<<<dim3(SEQ / 64, NHEAD, BATCH), 128, ATTN_SMEM_BYTES>>>(out);
}